// round 4
// baseline (speedup 1.0000x reference)
#include <cuda_runtime.h>
#include <math.h>
#include <stdint.h>

// Problem constants (fixed by the reference)
#define N_NODES 50000
#define N_EDGES 800000
#define IN_DIM  128
#define H_DIM   128
#define OUT_DIM 64
#define H1_DIM  512
#define EW_BLOCKS ((N_EDGES * 16 + 255) / 256)   // 50000

// alpha = 0.0 in reference -> x0/conv_w2 terms vanish.
#define BETA0 0.6931471805599453f   /* ln(2)   */
#define BETA1 0.4054651081081644f   /* ln(1.5) */

// ---------------- device scratch (static globals; no cudaMalloc allowed) ----
__device__ float  g_h1[N_NODES * H1_DIM];
__device__ float  g_h2[N_NODES * OUT_DIM];
__device__ float  g_glp[N_NODES * 128];   // [logits | lp] per row
__device__ float  g_P[OUT_DIM * OUT_DIM];
__device__ float  g_Wcat[OUT_DIM * 128];  // [w3 | w3@P]
__device__ float  g_bcat[128];            // [b3 | b3@P]
__device__ float  g_hA[N_NODES * H_DIM];
__device__ float  g_hB[N_NODES * H_DIM];
__device__ float  g_agg[N_NODES * H_DIM];
__device__ float  g_ewraw[N_EDGES];
__device__ float  g_ewp[N_EDGES];
__device__ float  g_normw[N_EDGES];
__device__ int    g_esrc[N_EDGES];
__device__ int    g_cnt[N_NODES];
__device__ int    g_cursor[N_NODES];
__device__ int    g_rowptr[N_NODES + 1];
__device__ double g_psum[EW_BLOCKS];
__device__ double g_psum2[EW_BLOCKS];
__device__ float  g_stats[2];
__device__ float  g_dinv[N_NODES];

// ---------------- tf32 tensor-core GEMM ------------------------------------
// C = relu?( alpha*(A@B) + bias + addA*A )   (addA path requires N==K)
// Block 128x64, 8 warps (4x2), warp tile 32x32, BK=16 (2 k-slabs of 8).
// smem holds fragments in mma-native order:
//   A: one LDS.128 per (warp, 16-row block, slab) -> regs a0..a3
//   B: one LDS.64  per (warp, 8-col block, slab)  -> regs b0..b1
// XOR swizzles keep both store and load conflict-(mostly)-free.
// Fragment double buffering hides LDS latency under MMAs.

__device__ __forceinline__ uint32_t f2tf32(float f)
{
    uint32_t o;
    asm("cvt.rna.tf32.f32 %0, %1;" : "=r"(o) : "f"(f));
    return o;
}

__device__ __forceinline__ void mma_tf32(float d[4], const uint32_t a[4], const uint32_t b[2])
{
    asm volatile(
        "mma.sync.aligned.m16n8k8.row.col.f32.tf32.tf32.f32 "
        "{%0,%1,%2,%3}, {%4,%5,%6,%7}, {%8,%9}, {%0,%1,%2,%3};"
        : "+f"(d[0]), "+f"(d[1]), "+f"(d[2]), "+f"(d[3])
        : "r"(a[0]), "r"(a[1]), "r"(a[2]), "r"(a[3]), "r"(b[0]), "r"(b[1]));
}

__device__ __forceinline__ int vB(int b8) { return ((b8 & 3) << 3) | ((b8 >> 2) << 1); }

__global__ __launch_bounds__(256, 2)
void gemm_tc(const float* __restrict__ A, const float* __restrict__ B,
             const float* __restrict__ bias, float* __restrict__ C,
             int M, int N, int K, float alpha, float addA, int do_relu)
{
    // per buffer: A = 2 slabs * 8 block16 * 128 words ; B = 2 slabs * 8 block8 * 64 words
    __shared__ uint32_t As[2][2048];
    __shared__ uint32_t Bs[2][1024];

    const int tid  = threadIdx.x;
    const int lane = tid & 31;
    const int wid  = tid >> 5;
    const int wm   = wid & 3;        // warp m index (0..3): 32-row slab
    const int wn   = wid >> 2;       // warp n index (0..1): 32-col slab
    const int gid  = lane >> 2;
    const int tig  = lane & 3;
    const int m0   = blockIdx.x * 128;
    const int n0   = blockIdx.y * 64;

    // ---- staging thread roles ----
    // A: thread -> row = tid>>1 (0..127), q = tid&1 -> slab q, k = q*8 .. q*8+7 (2 float4)
    const int arow = tid >> 1;
    const int aq   = tid & 1;
    const bool av  = (m0 + arow) < M;
    const float* Ap = A + (size_t)(m0 + arow) * K + aq * 8;
    // precomputed A store base
    const int ablk16 = arow >> 4;
    const int agid   = arow & 7;
    const int arbit  = (arow >> 3) & 1;
    const int asw    = agid & 3;
    const int abase  = aq * 1024 + ablk16 * 128 + agid * 16;
    // B: thread -> k = tid>>4 (0..15), n = (tid&15)*4 .. +3 (1 float4)
    const int bkk  = tid >> 4;
    const int bn4  = (tid & 15) * 4;
    const int bslab = bkk >> 3;
    const int btig  = bkk & 3;
    const int br    = (bkk >> 2) & 1;
    const float* Bp = B + (size_t)bkk * N + n0 + bn4;

    float d[2][4][4];
#pragma unroll
    for (int f = 0; f < 2; f++)
#pragma unroll
        for (int g = 0; g < 4; g++)
#pragma unroll
            for (int i = 0; i < 4; i++) d[f][g][i] = 0.f;

    // fragment regs, double buffered
    uint32_t af[2][2][4];
    uint32_t bf[2][4][2];

    // fragment load addresses (word offsets, constant across tiles)
    int aoff[2];   // [f] within-buffer offset minus slab term
#pragma unroll
    for (int f = 0; f < 2; f++)
        aoff[f] = (wm * 2 + f) * 128 + gid * 16 + ((tig ^ (gid & 3)) << 2);
    int boff[4];
#pragma unroll
    for (int g = 0; g < 4; g++) {
        int b8 = wn * 4 + g;
        boff[g] = b8 * 64 + ((lane * 2) ^ vB(b8));
    }

    const int ntiles = K >> 4;
    const float4 z4 = make_float4(0.f, 0.f, 0.f, 0.f);

    float4 a4a, a4b, b4;

    // ---- stage tile 0 ----
    a4a = av ? *(const float4*)Ap : z4;
    a4b = av ? *(const float4*)(Ap + 4) : z4;
    b4  = *(const float4*)Bp;
    {
        const float va[8] = {a4a.x, a4a.y, a4a.z, a4a.w, a4b.x, a4b.y, a4b.z, a4b.w};
#pragma unroll
        for (int h = 0; h < 2; h++)
#pragma unroll
            for (int j = 0; j < 4; j++)
                As[0][abase + ((j ^ asw) << 2) + (arbit | (h << 1))] = f2tf32(va[h * 4 + j]);
        const float vb[4] = {b4.x, b4.y, b4.z, b4.w};
#pragma unroll
        for (int j = 0; j < 4; j++) {
            int n = bn4 + j;
            int b8 = n >> 3, gg = n & 7;
            Bs[0][bslab * 512 + b8 * 64 + ((((gg << 2) + btig) << 1 | br) ^ vB(b8))] = f2tf32(vb[j]);
        }
    }
    __syncthreads();

    // load fragments (buf 0, slab 0) into fb 0
#pragma unroll
    for (int f = 0; f < 2; f++) *(uint4*)af[0][f] = *(const uint4*)&As[0][aoff[f]];
#pragma unroll
    for (int g = 0; g < 4; g++) *(uint2*)bf[0][g] = *(const uint2*)&Bs[0][boff[g]];

    for (int t = 0; t < ntiles; t++) {
        const int cur = t & 1;
        const int nxt = cur ^ 1;
        const bool more = (t + 1) < ntiles;

        // issue global loads for tile t+1 (latency hidden under both MMA batches)
        if (more) {
            const float* Apn = Ap + (t + 1) * 16;
            a4a = av ? *(const float4*)Apn : z4;
            a4b = av ? *(const float4*)(Apn + 4) : z4;
            b4 = *(const float4*)(Bp + (size_t)(t + 1) * 16 * N);
        }

        // prefetch fragments (cur, slab 1) into fb 1
#pragma unroll
        for (int f = 0; f < 2; f++) *(uint4*)af[1][f] = *(const uint4*)&As[cur][1024 + aoff[f]];
#pragma unroll
        for (int g = 0; g < 4; g++) *(uint2*)bf[1][g] = *(const uint2*)&Bs[cur][512 + boff[g]];

        // MMAs on slab 0 (fb 0)
#pragma unroll
        for (int f = 0; f < 2; f++)
#pragma unroll
            for (int g = 0; g < 4; g++)
                mma_tf32(d[f][g], af[0][f], bf[0][g]);

        if (more) {
            // store staged tile t+1 into buffer nxt
            const float va[8] = {a4a.x, a4a.y, a4a.z, a4a.w, a4b.x, a4b.y, a4b.z, a4b.w};
#pragma unroll
            for (int h = 0; h < 2; h++)
#pragma unroll
                for (int j = 0; j < 4; j++)
                    As[nxt][abase + ((j ^ asw) << 2) + (arbit | (h << 1))] = f2tf32(va[h * 4 + j]);
            const float vb[4] = {b4.x, b4.y, b4.z, b4.w};
#pragma unroll
            for (int j = 0; j < 4; j++) {
                int n = bn4 + j;
                int b8 = n >> 3, gg = n & 7;
                Bs[nxt][bslab * 512 + b8 * 64 + ((((gg << 2) + btig) << 1 | br) ^ vB(b8))] = f2tf32(vb[j]);
            }
            __syncthreads();
            // prefetch fragments (nxt, slab 0) into fb 0
#pragma unroll
            for (int f = 0; f < 2; f++) *(uint4*)af[0][f] = *(const uint4*)&As[nxt][aoff[f]];
#pragma unroll
            for (int g = 0; g < 4; g++) *(uint2*)bf[0][g] = *(const uint2*)&Bs[nxt][boff[g]];
        }

        // MMAs on slab 1 (fb 1)
#pragma unroll
        for (int f = 0; f < 2; f++)
#pragma unroll
            for (int g = 0; g < 4; g++)
                mma_tf32(d[f][g], af[1][f], bf[1][g]);
    }

    // epilogue: d0,d1 -> (row, col..col+1); d2,d3 -> (row+8, ...)
#pragma unroll
    for (int f = 0; f < 2; f++) {
        const int r0 = m0 + wm * 32 + f * 16 + gid;
#pragma unroll
        for (int g = 0; g < 4; g++) {
            const int cc = n0 + wn * 32 + g * 8 + 2 * tig;
#pragma unroll
            for (int h = 0; h < 2; h++) {
                const int gm = r0 + h * 8;
                if (gm >= M) continue;
                float v0 = alpha * d[f][g][2 * h + 0];
                float v1 = alpha * d[f][g][2 * h + 1];
                if (bias) {
                    float2 bb = *(const float2*)&bias[cc];
                    v0 += bb.x; v1 += bb.y;
                }
                if (addA != 0.f) {  // residual path: N == K
                    float2 r = *(const float2*)&A[(size_t)gm * K + cc];
                    v0 += addA * r.x; v1 += addA * r.y;
                }
                if (do_relu) { v0 = fmaxf(v0, 0.f); v1 = fmaxf(v1, 0.f); }
                *(float2*)&C[(size_t)gm * N + cc] = make_float2(v0, v1);
            }
        }
    }
}

// ---------------- P = relu(SCALE * parsing[0]) ----------------
__global__ void p_kernel(const float* __restrict__ parsing)
{
    int i = blockIdx.x * blockDim.x + threadIdx.x;
    if (i < OUT_DIM * OUT_DIM) g_P[i] = fmaxf(2.0f * parsing[i], 0.0f);
}

// ---------------- Wcat = [w3 | w3@P], bcat = [b3 | b3@P] --------------------
__global__ void wcat_kernel(const float* __restrict__ w3, const float* __restrict__ b3)
{
    int idx = blockIdx.x * 256 + threadIdx.x;
    if (idx < 64 * 64) {
        int k = idx >> 6, j = idx & 63;
        g_Wcat[k * 128 + j] = w3[k * 64 + j];
        float s = 0.f;
        for (int i = 0; i < 64; i++) s += w3[k * 64 + i] * g_P[i * 64 + j];
        g_Wcat[k * 128 + 64 + j] = s;
    } else if (idx < 64 * 64 + 64) {
        int j = idx - 64 * 64;
        g_bcat[j] = b3[j];
        float s = 0.f;
        for (int i = 0; i < 64; i++) s += b3[i] * g_P[i * 64 + j];
        g_bcat[64 + j] = s;
    }
}

// ---------------- edge weights: ew[e] = dot(logits[row[e]], lp[col[e]]) ------
__global__ void ew_kernel(const int* __restrict__ erow, const int* __restrict__ ecol)
{
    int t = blockIdx.x * 256 + threadIdx.x;
    int e = t >> 4;
    int l = t & 15;
    float v = 0.f;
    if (e < N_EDGES) {
        int r = erow[e], c = ecol[e];
        float4 a = *(const float4*)(g_glp + (size_t)r * 128 + l * 4);
        float4 b = *(const float4*)(g_glp + (size_t)c * 128 + 64 + l * 4);
        v = a.x * b.x + a.y * b.y + a.z * b.z + a.w * b.w;
    }
#pragma unroll
    for (int off = 8; off > 0; off >>= 1)
        v += __shfl_xor_sync(0xffffffffu, v, off);
    if (l == 0 && e < N_EDGES) g_ewraw[e] = v;

    double s  = (l == 0 && e < N_EDGES) ? (double)v : 0.0;
    double s2 = (l == 0 && e < N_EDGES) ? (double)v * (double)v : 0.0;
    __shared__ double sh1[256];
    __shared__ double sh2[256];
    sh1[threadIdx.x] = s; sh2[threadIdx.x] = s2;
    __syncthreads();
    for (int off = 128; off > 0; off >>= 1) {
        if (threadIdx.x < off) {
            sh1[threadIdx.x] += sh1[threadIdx.x + off];
            sh2[threadIdx.x] += sh2[threadIdx.x + off];
        }
        __syncthreads();
    }
    if (threadIdx.x == 0) { g_psum[blockIdx.x] = sh1[0]; g_psum2[blockIdx.x] = sh2[0]; }
}

__global__ void stats_kernel()
{
    int t = threadIdx.x;
    double s = 0.0, s2 = 0.0;
    for (int i = t; i < EW_BLOCKS; i += 1024) { s += g_psum[i]; s2 += g_psum2[i]; }
    __shared__ double sh1[1024];
    __shared__ double sh2[1024];
    sh1[t] = s; sh2[t] = s2;
    __syncthreads();
    for (int off = 512; off > 0; off >>= 1) {
        if (t < off) { sh1[t] += sh1[t + off]; sh2[t] += sh2[t + off]; }
        __syncthreads();
    }
    if (t == 0) {
        double sum = sh1[0], sumsq = sh2[0];
        double mean = sum / (double)N_EDGES;
        double var = (sumsq - sum * sum / (double)N_EDGES) / (double)(N_EDGES - 1);
        g_stats[0] = (float)mean;
        g_stats[1] = (float)sqrt(1e-4 / var);
    }
}

// ---------------- CSR build (sorted by destination col) ----------------------
__global__ void count_kernel(const int* __restrict__ ecol)
{
    int e = blockIdx.x * blockDim.x + threadIdx.x;
    if (e < N_EDGES) atomicAdd(&g_cnt[ecol[e]], 1);
}

__global__ void scan_kernel()
{
    __shared__ int sh[1024];
    __shared__ int s_carry;
    int t = threadIdx.x;
    if (t == 0) { s_carry = 0; g_rowptr[0] = 0; }
    __syncthreads();
    for (int base = 0; base < N_NODES; base += 1024) {
        int v = (base + t < N_NODES) ? g_cnt[base + t] : 0;
        sh[t] = v;
        __syncthreads();
        for (int off = 1; off < 1024; off <<= 1) {
            int add = (t >= off) ? sh[t - off] : 0;
            __syncthreads();
            sh[t] += add;
            __syncthreads();
        }
        int inc = sh[t] + s_carry;
        if (base + t < N_NODES) {
            g_rowptr[base + t + 1] = inc;
            g_cursor[base + t] = inc - v;
        }
        int total = sh[1023];
        __syncthreads();
        if (t == 0) s_carry += total;
        __syncthreads();
    }
}

__global__ void scatter_kernel(const int* __restrict__ erow, const int* __restrict__ ecol)
{
    int e = blockIdx.x * blockDim.x + threadIdx.x;
    if (e < N_EDGES) {
        int p = atomicAdd(&g_cursor[ecol[e]], 1);
        g_esrc[p] = erow[e];
        g_ewp[p] = g_ewraw[e];
    }
}

__global__ void deg_kernel()
{
    int warp = (blockIdx.x * blockDim.x + threadIdx.x) >> 5;
    int lane = threadIdx.x & 31;
    if (warp >= N_NODES) return;
    float mean = g_stats[0], scale = g_stats[1];
    int s0 = g_rowptr[warp], s1 = g_rowptr[warp + 1];
    float s = 0.f;
    for (int p = s0 + lane; p < s1; p += 32) {
        float w = (g_ewp[p] - mean) * scale + 1.0f;
        g_ewp[p] = w;
        s += w;
    }
#pragma unroll
    for (int off = 16; off > 0; off >>= 1)
        s += __shfl_xor_sync(0xffffffffu, s, off);
    if (lane == 0) {
        float deg = s + 1.0f;
        g_dinv[warp] = (deg > 0.f) ? rsqrtf(deg) : 0.f;
    }
}

__global__ void normw_kernel()
{
    int warp = (blockIdx.x * blockDim.x + threadIdx.x) >> 5;
    int lane = threadIdx.x & 31;
    if (warp >= N_NODES) return;
    float di = g_dinv[warp];
    int s0 = g_rowptr[warp], s1 = g_rowptr[warp + 1];
    for (int p = s0 + lane; p < s1; p += 32)
        g_normw[p] = g_dinv[g_esrc[p]] * g_ewp[p] * di;
}

// ---------------- SpMM: agg[n] = sum_in normw*h[src] + dinv[n]^2 * h[n] ------
__global__ void spmm_kernel(const float* __restrict__ hin, float* __restrict__ agg)
{
    int warp = (blockIdx.x * blockDim.x + threadIdx.x) >> 5;
    int lane = threadIdx.x & 31;
    if (warp >= N_NODES) return;
    const float4* h4 = (const float4*)hin;
    float di = g_dinv[warp];
    float selfw = di * di;
    float4 hv = h4[(size_t)warp * 32 + lane];
    float4 acc;
    acc.x = selfw * hv.x; acc.y = selfw * hv.y; acc.z = selfw * hv.z; acc.w = selfw * hv.w;
    int s0 = g_rowptr[warp], s1 = g_rowptr[warp + 1];
    for (int p = s0; p < s1; p++) {
        float w = g_normw[p];
        int src = g_esrc[p];
        float4 v = h4[(size_t)src * 32 + lane];
        acc.x += w * v.x; acc.y += w * v.y; acc.z += w * v.z; acc.w += w * v.w;
    }
    ((float4*)agg)[(size_t)warp * 32 + lane] = acc;
}

// ---------------- launch ----------------------------------------------------
extern "C" void kernel_launch(void* const* d_in, const int* in_sizes, int n_in,
                              void* d_out, int out_size)
{
    const float* x       = (const float*)d_in[0];
    const int*   eidx    = (const int*)d_in[1];
    const float* w1      = (const float*)d_in[2];
    const float* b1      = (const float*)d_in[3];
    const float* w2      = (const float*)d_in[4];
    const float* b2      = (const float*)d_in[5];
    const float* w3      = (const float*)d_in[6];
    const float* b3      = (const float*)d_in[7];
    const float* parsing = (const float*)d_in[8];
    const float* l0w     = (const float*)d_in[9];
    const float* l0b     = (const float*)d_in[10];
    const float* l1w     = (const float*)d_in[11];
    const float* l1b     = (const float*)d_in[12];
    const float* cw1     = (const float*)d_in[13];
    float* out = (float*)d_out;
    const int* erow = eidx;
    const int* ecol = eidx + N_EDGES;

    float *p_h1, *p_h2, *p_glp, *p_Wcat, *p_bcat, *p_hA, *p_hB, *p_agg;
    int *p_cnt;
    cudaGetSymbolAddress((void**)&p_h1, g_h1);
    cudaGetSymbolAddress((void**)&p_h2, g_h2);
    cudaGetSymbolAddress((void**)&p_glp, g_glp);
    cudaGetSymbolAddress((void**)&p_Wcat, g_Wcat);
    cudaGetSymbolAddress((void**)&p_bcat, g_bcat);
    cudaGetSymbolAddress((void**)&p_hA, g_hA);
    cudaGetSymbolAddress((void**)&p_hB, g_hB);
    cudaGetSymbolAddress((void**)&p_agg, g_agg);
    cudaGetSymbolAddress((void**)&p_cnt, g_cnt);

    const int gmx = (N_NODES + 127) / 128;  // 391

    p_kernel<<<4, 1024>>>(parsing);
    wcat_kernel<<<17, 256>>>(w3, b3);

    // MLP: x -> h1 -> h2 -> [logits | lp]
    gemm_tc<<<dim3(gmx, 8), 256>>>(x, w1, b1, p_h1, N_NODES, 512, IN_DIM, 1.f, 0.f, 1);
    gemm_tc<<<dim3(gmx, 1), 256>>>(p_h1, w2, b2, p_h2, N_NODES, OUT_DIM, H1_DIM, 1.f, 0.f, 1);
    gemm_tc<<<dim3(gmx, 2), 256>>>(p_h2, p_Wcat, p_bcat, p_glp, N_NODES, 128, OUT_DIM, 1.f, 0.f, 0);
    // x0 = relu(x @ lin0 + b)
    gemm_tc<<<dim3(gmx, 2), 256>>>(x, l0w, l0b, p_hA, N_NODES, H_DIM, IN_DIM, 1.f, 0.f, 1);

    // edge weights + stats
    ew_kernel<<<EW_BLOCKS, 256>>>(erow, ecol);
    stats_kernel<<<1, 1024>>>();

    // CSR build
    cudaMemsetAsync(p_cnt, 0, N_NODES * sizeof(int));
    count_kernel<<<(N_EDGES + 255) / 256, 256>>>(ecol);
    scan_kernel<<<1, 1024>>>();
    scatter_kernel<<<(N_EDGES + 255) / 256, 256>>>(erow, ecol);
    deg_kernel<<<(N_NODES + 7) / 8, 256>>>();
    normw_kernel<<<(N_NODES + 7) / 8, 256>>>();

    // layer 0
    spmm_kernel<<<(N_NODES + 7) / 8, 256>>>(p_hA, p_agg);
    gemm_tc<<<dim3(gmx, 2), 256>>>(p_agg, cw1, nullptr, p_hB,
                                   N_NODES, H_DIM, H_DIM, BETA0, 1.f - BETA0, 1);
    // layer 1
    spmm_kernel<<<(N_NODES + 7) / 8, 256>>>(p_hB, p_agg);
    gemm_tc<<<dim3(gmx, 2), 256>>>(p_agg, cw1 + H_DIM * H_DIM, nullptr, p_hA,
                                   N_NODES, H_DIM, H_DIM, BETA1, 1.f - BETA1, 1);
    // output
    gemm_tc<<<dim3(gmx, 1), 256>>>(p_hA, l1w, l1b, out, N_NODES, OUT_DIM, H_DIM, 1.f, 0.f, 0);
}

// round 5
// speedup vs baseline: 1.1217x; 1.1217x over previous
#include <cuda_runtime.h>
#include <math.h>
#include <stdint.h>

// Problem constants (fixed by the reference)
#define N_NODES 50000
#define N_EDGES 800000
#define IN_DIM  128
#define H_DIM   128
#define OUT_DIM 64
#define H1_DIM  512
#define EW_BLOCKS ((N_EDGES * 16 + 255) / 256)   // 50000

// alpha = 0.0 in reference -> x0/conv_w2 terms vanish.
#define BETA0 0.6931471805599453f   /* ln(2)   */
#define BETA1 0.4054651081081644f   /* ln(1.5) */

// ---------------- device scratch (static globals; no cudaMalloc allowed) ----
__device__ float  g_xt[N_NODES * IN_DIM];     // tf32-rounded x
__device__ float  g_w1t[IN_DIM * 512];
__device__ float  g_w2t[512 * OUT_DIM];
__device__ float  g_l0wt[IN_DIM * H_DIM];
__device__ float  g_l1wt[H_DIM * OUT_DIM];
__device__ float  g_cw1t[2 * H_DIM * H_DIM];
__device__ float  g_h1[N_NODES * H1_DIM];
__device__ float  g_h2[N_NODES * OUT_DIM];
__device__ float  g_glp[N_NODES * 128];   // [logits | lp] per row
__device__ float  g_P[OUT_DIM * OUT_DIM];
__device__ float  g_Wcat[OUT_DIM * 128];  // [w3 | w3@P], tf32-rounded
__device__ float  g_bcat[128];            // [b3 | b3@P]
__device__ float  g_hA[N_NODES * H_DIM];
__device__ float  g_hB[N_NODES * H_DIM];
__device__ float  g_agg[N_NODES * H_DIM];
__device__ float  g_ewraw[N_EDGES];
__device__ float  g_ewp[N_EDGES];
__device__ float  g_normw[N_EDGES];
__device__ int    g_esrc[N_EDGES];
__device__ int    g_cnt[N_NODES];
__device__ int    g_cursor[N_NODES];
__device__ int    g_rowptr[N_NODES + 1];
__device__ double g_psum[EW_BLOCKS];
__device__ double g_psum2[EW_BLOCKS];
__device__ float  g_stats[2];
__device__ float  g_dinv[N_NODES];

// ---------------- tf32 helpers ----------------------------------------------
__device__ __forceinline__ uint32_t f2tf32(float f)
{
    uint32_t o;
    asm("cvt.rna.tf32.f32 %0, %1;" : "=r"(o) : "f"(f));
    return o;
}
__device__ __forceinline__ float tf32r(float f) { return __uint_as_float(f2tf32(f)); }

__device__ __forceinline__ void mma_tf32(float d[4], const uint32_t a[4], const uint32_t b[2])
{
    asm volatile(
        "mma.sync.aligned.m16n8k8.row.col.f32.tf32.tf32.f32 "
        "{%0,%1,%2,%3}, {%4,%5,%6,%7}, {%8,%9}, {%0,%1,%2,%3};"
        : "+f"(d[0]), "+f"(d[1]), "+f"(d[2]), "+f"(d[3])
        : "r"(a[0]), "r"(a[1]), "r"(a[2]), "r"(a[3]), "r"(b[0]), "r"(b[1]));
}

__device__ __forceinline__ void cpa16(uint32_t dst, const float* src, uint32_t sz)
{
    asm volatile("cp.async.cg.shared.global [%0], [%1], 16, %2;"
                 :: "r"(dst), "l"(src), "r"(sz));
}
__device__ __forceinline__ void cpa_commit() { asm volatile("cp.async.commit_group;"); }
__device__ __forceinline__ void cpa_wait1()  { asm volatile("cp.async.wait_group 1;"); }

// ---------------- tf32 tensor-core GEMM (cp.async 3-stage) ------------------
// C = relu?( alpha*(A@B) + bias + addA*A ) [+ tf32 rounding of output]
// A, B must already be tf32-rounded fp32. Block 128x64, 8 warps (4x2),
// warp tile 32x32, BK=16. smem: A [m][k] stride 20, B [k][n] stride 72
// (conflict-free fragment loads, 16B-aligned rows for cp.async).

#define SKA 20
#define SKB 72
#define A_WORDS (128 * SKA)   // 2560
#define B_WORDS (16 * SKB)    // 1152

__global__ __launch_bounds__(256, 3)
void gemm_tc(const float* __restrict__ A, const float* __restrict__ B,
             const float* __restrict__ bias, float* __restrict__ C,
             int M, int N, int K, float alpha, float addA, int do_relu, int round_out)
{
    __shared__ float As[3 * A_WORDS];
    __shared__ float Bs[3 * B_WORDS];

    const int tid  = threadIdx.x;
    const int lane = tid & 31;
    const int wid  = tid >> 5;
    const int wm   = wid & 3;
    const int wn   = wid >> 2;
    const int gid  = lane >> 2;
    const int tig  = lane & 3;
    const int m0   = blockIdx.x * 128;
    const int n0   = blockIdx.y * 64;

    // staging roles
    const int am     = tid >> 1;            // A row 0..127
    const int akq    = (tid & 1) * 2;       // chunks akq, akq+1 (k = kq*4)
    const uint32_t asz = ((m0 + am) < M) ? 16u : 0u;
    const float* Apt = A + (size_t)(m0 + am) * K + akq * 4;
    const int bk     = tid >> 4;            // B k-row 0..15
    const int bn4    = (tid & 15) * 4;
    const float* Bpt = B + (size_t)bk * N + n0 + bn4;

    uint32_t as_base = (uint32_t)__cvta_generic_to_shared(As);
    uint32_t bs_base = (uint32_t)__cvta_generic_to_shared(Bs);
    const uint32_t adst0 = as_base + (am * SKA + akq * 4) * 4;
    const uint32_t bdst0 = bs_base + (bk * SKB + bn4) * 4;

    float d[2][4][4];
#pragma unroll
    for (int f = 0; f < 2; f++)
#pragma unroll
        for (int g = 0; g < 4; g++)
#pragma unroll
            for (int i = 0; i < 4; i++) d[f][g][i] = 0.f;

    const int ntiles = K >> 4;

    // prefetch tiles 0 and 1
#pragma unroll
    for (int t = 0; t < 2; t++) {
        const uint32_t ad = adst0 + t * (A_WORDS * 4);
        const uint32_t bd = bdst0 + t * (B_WORDS * 4);
        cpa16(ad, Apt + t * 16, asz);
        cpa16(ad + 16, Apt + t * 16 + 4, asz);
        cpa16(bd, Bpt + (size_t)t * 16 * N, 16);
        cpa_commit();
    }
    cpa_wait1();
    __syncthreads();

    for (int t = 0; t < ntiles; t++) {
        // issue tile t+2 into slot (t+2)%3
        const int tp = t + 2;
        if (tp < ntiles) {
            const int sl = tp - (tp / 3) * 3;
            const uint32_t ad = adst0 + sl * (A_WORDS * 4);
            const uint32_t bd = bdst0 + sl * (B_WORDS * 4);
            cpa16(ad, Apt + tp * 16, asz);
            cpa16(ad + 16, Apt + tp * 16 + 4, asz);
            cpa16(bd, Bpt + (size_t)tp * 16 * N, 16);
        }
        cpa_commit();

        // compute tile t from slot t%3
        const int s = t - (t / 3) * 3;
        const float* Ab = As + s * A_WORDS;
        const float* Bb = Bs + s * B_WORDS;
#pragma unroll
        for (int ks = 0; ks < 16; ks += 8) {
            uint32_t af[2][4];
#pragma unroll
            for (int f = 0; f < 2; f++) {
                const int rb = wm * 32 + f * 16 + gid;
                af[f][0] = __float_as_uint(Ab[rb * SKA + ks + tig]);
                af[f][1] = __float_as_uint(Ab[(rb + 8) * SKA + ks + tig]);
                af[f][2] = __float_as_uint(Ab[rb * SKA + ks + tig + 4]);
                af[f][3] = __float_as_uint(Ab[(rb + 8) * SKA + ks + tig + 4]);
            }
            uint32_t bf[4][2];
#pragma unroll
            for (int g = 0; g < 4; g++) {
                const int nb = wn * 32 + g * 8 + gid;
                bf[g][0] = __float_as_uint(Bb[(ks + tig) * SKB + nb]);
                bf[g][1] = __float_as_uint(Bb[(ks + tig + 4) * SKB + nb]);
            }
#pragma unroll
            for (int f = 0; f < 2; f++)
#pragma unroll
                for (int g = 0; g < 4; g++)
                    mma_tf32(d[f][g], af[f], bf[g]);
        }
        cpa_wait1();
        __syncthreads();
    }

    // epilogue
#pragma unroll
    for (int f = 0; f < 2; f++) {
        const int r0 = m0 + wm * 32 + f * 16 + gid;
#pragma unroll
        for (int g = 0; g < 4; g++) {
            const int cc = n0 + wn * 32 + g * 8 + 2 * tig;
#pragma unroll
            for (int h = 0; h < 2; h++) {
                const int gm = r0 + h * 8;
                if (gm >= M) continue;
                float v0 = alpha * d[f][g][2 * h + 0];
                float v1 = alpha * d[f][g][2 * h + 1];
                if (bias) {
                    float2 bb = *(const float2*)&bias[cc];
                    v0 += bb.x; v1 += bb.y;
                }
                if (addA != 0.f) {  // residual path: N == K
                    float2 r = *(const float2*)&A[(size_t)gm * K + cc];
                    v0 += addA * r.x; v1 += addA * r.y;
                }
                if (do_relu) { v0 = fmaxf(v0, 0.f); v1 = fmaxf(v1, 0.f); }
                if (round_out) { v0 = tf32r(v0); v1 = tf32r(v1); }
                *(float2*)&C[(size_t)gm * N + cc] = make_float2(v0, v1);
            }
        }
    }
}

// ---------------- tf32 rounding copy ----------------------------------------
__global__ void rt_kernel(const float* __restrict__ s, float* __restrict__ d, int n)
{
    int i = blockIdx.x * 256 + threadIdx.x;
    if (i < n) d[i] = tf32r(s[i]);
}

// ---------------- P = relu(SCALE * parsing[0]) ----------------
__global__ void p_kernel(const float* __restrict__ parsing)
{
    int i = blockIdx.x * blockDim.x + threadIdx.x;
    if (i < OUT_DIM * OUT_DIM) g_P[i] = fmaxf(2.0f * parsing[i], 0.0f);
}

// ---------------- Wcat = [w3 | w3@P], bcat = [b3 | b3@P] (tf32-rounded W) ---
__global__ void wcat_kernel(const float* __restrict__ w3, const float* __restrict__ b3)
{
    int idx = blockIdx.x * 256 + threadIdx.x;
    if (idx < 64 * 64) {
        int k = idx >> 6, j = idx & 63;
        g_Wcat[k * 128 + j] = tf32r(w3[k * 64 + j]);
        float s = 0.f;
        for (int i = 0; i < 64; i++) s += w3[k * 64 + i] * g_P[i * 64 + j];
        g_Wcat[k * 128 + 64 + j] = tf32r(s);
    } else if (idx < 64 * 64 + 64) {
        int j = idx - 64 * 64;
        g_bcat[j] = b3[j];
        float s = 0.f;
        for (int i = 0; i < 64; i++) s += b3[i] * g_P[i * 64 + j];
        g_bcat[64 + j] = s;
    }
}

// ---------------- edge weights: ew[e] = dot(logits[row[e]], lp[col[e]]) ------
__global__ void ew_kernel(const int* __restrict__ erow, const int* __restrict__ ecol)
{
    int t = blockIdx.x * 256 + threadIdx.x;
    int e = t >> 4;
    int l = t & 15;
    float v = 0.f;
    if (e < N_EDGES) {
        int r = erow[e], c = ecol[e];
        float4 a = *(const float4*)(g_glp + (size_t)r * 128 + l * 4);
        float4 b = *(const float4*)(g_glp + (size_t)c * 128 + 64 + l * 4);
        v = a.x * b.x + a.y * b.y + a.z * b.z + a.w * b.w;
    }
#pragma unroll
    for (int off = 8; off > 0; off >>= 1)
        v += __shfl_xor_sync(0xffffffffu, v, off);
    if (l == 0 && e < N_EDGES) g_ewraw[e] = v;

    double s  = (l == 0 && e < N_EDGES) ? (double)v : 0.0;
    double s2 = (l == 0 && e < N_EDGES) ? (double)v * (double)v : 0.0;
    __shared__ double sh1[256];
    __shared__ double sh2[256];
    sh1[threadIdx.x] = s; sh2[threadIdx.x] = s2;
    __syncthreads();
    for (int off = 128; off > 0; off >>= 1) {
        if (threadIdx.x < off) {
            sh1[threadIdx.x] += sh1[threadIdx.x + off];
            sh2[threadIdx.x] += sh2[threadIdx.x + off];
        }
        __syncthreads();
    }
    if (threadIdx.x == 0) { g_psum[blockIdx.x] = sh1[0]; g_psum2[blockIdx.x] = sh2[0]; }
}

__global__ void stats_kernel()
{
    int t = threadIdx.x;
    double s = 0.0, s2 = 0.0;
    for (int i = t; i < EW_BLOCKS; i += 1024) { s += g_psum[i]; s2 += g_psum2[i]; }
    __shared__ double sh1[1024];
    __shared__ double sh2[1024];
    sh1[t] = s; sh2[t] = s2;
    __syncthreads();
    for (int off = 512; off > 0; off >>= 1) {
        if (t < off) { sh1[t] += sh1[t + off]; sh2[t] += sh2[t + off]; }
        __syncthreads();
    }
    if (t == 0) {
        double sum = sh1[0], sumsq = sh2[0];
        double mean = sum / (double)N_EDGES;
        double var = (sumsq - sum * sum / (double)N_EDGES) / (double)(N_EDGES - 1);
        g_stats[0] = (float)mean;
        g_stats[1] = (float)sqrt(1e-4 / var);
    }
}

// ---------------- CSR build (sorted by destination col) ----------------------
__global__ void count_kernel(const int* __restrict__ ecol)
{
    int e = blockIdx.x * blockDim.x + threadIdx.x;
    if (e < N_EDGES) atomicAdd(&g_cnt[ecol[e]], 1);
}

__global__ void scan_kernel()
{
    __shared__ int sh[1024];
    __shared__ int s_carry;
    int t = threadIdx.x;
    if (t == 0) { s_carry = 0; g_rowptr[0] = 0; }
    __syncthreads();
    for (int base = 0; base < N_NODES; base += 1024) {
        int v = (base + t < N_NODES) ? g_cnt[base + t] : 0;
        sh[t] = v;
        __syncthreads();
        for (int off = 1; off < 1024; off <<= 1) {
            int add = (t >= off) ? sh[t - off] : 0;
            __syncthreads();
            sh[t] += add;
            __syncthreads();
        }
        int inc = sh[t] + s_carry;
        if (base + t < N_NODES) {
            g_rowptr[base + t + 1] = inc;
            g_cursor[base + t] = inc - v;
        }
        int total = sh[1023];
        __syncthreads();
        if (t == 0) s_carry += total;
        __syncthreads();
    }
}

__global__ void scatter_kernel(const int* __restrict__ erow, const int* __restrict__ ecol)
{
    int e = blockIdx.x * blockDim.x + threadIdx.x;
    if (e < N_EDGES) {
        int p = atomicAdd(&g_cursor[ecol[e]], 1);
        g_esrc[p] = erow[e];
        g_ewp[p] = g_ewraw[e];
    }
}

__global__ void deg_kernel()
{
    int warp = (blockIdx.x * blockDim.x + threadIdx.x) >> 5;
    int lane = threadIdx.x & 31;
    if (warp >= N_NODES) return;
    float mean = g_stats[0], scale = g_stats[1];
    int s0 = g_rowptr[warp], s1 = g_rowptr[warp + 1];
    float s = 0.f;
    for (int p = s0 + lane; p < s1; p += 32) {
        float w = (g_ewp[p] - mean) * scale + 1.0f;
        g_ewp[p] = w;
        s += w;
    }
#pragma unroll
    for (int off = 16; off > 0; off >>= 1)
        s += __shfl_xor_sync(0xffffffffu, s, off);
    if (lane == 0) {
        float deg = s + 1.0f;
        g_dinv[warp] = (deg > 0.f) ? rsqrtf(deg) : 0.f;
    }
}

__global__ void normw_kernel()
{
    int warp = (blockIdx.x * blockDim.x + threadIdx.x) >> 5;
    int lane = threadIdx.x & 31;
    if (warp >= N_NODES) return;
    float di = g_dinv[warp];
    int s0 = g_rowptr[warp], s1 = g_rowptr[warp + 1];
    for (int p = s0 + lane; p < s1; p += 32)
        g_normw[p] = g_dinv[g_esrc[p]] * g_ewp[p] * di;
}

// ---- SpMM: agg[n] = tf32round( sum_in normw*h[src] + dinv[n]^2 * h[n] ) ----
__global__ void spmm_kernel(const float* __restrict__ hin, float* __restrict__ agg)
{
    int warp = (blockIdx.x * blockDim.x + threadIdx.x) >> 5;
    int lane = threadIdx.x & 31;
    if (warp >= N_NODES) return;
    const float4* h4 = (const float4*)hin;
    float di = g_dinv[warp];
    float selfw = di * di;
    float4 hv = h4[(size_t)warp * 32 + lane];
    float4 acc;
    acc.x = selfw * hv.x; acc.y = selfw * hv.y; acc.z = selfw * hv.z; acc.w = selfw * hv.w;
    int s0 = g_rowptr[warp], s1 = g_rowptr[warp + 1];
    for (int p = s0; p < s1; p++) {
        float w = g_normw[p];
        int src = g_esrc[p];
        float4 v = h4[(size_t)src * 32 + lane];
        acc.x += w * v.x; acc.y += w * v.y; acc.z += w * v.z; acc.w += w * v.w;
    }
    acc.x = tf32r(acc.x); acc.y = tf32r(acc.y);
    acc.z = tf32r(acc.z); acc.w = tf32r(acc.w);
    ((float4*)agg)[(size_t)warp * 32 + lane] = acc;
}

// ---------------- launch ----------------------------------------------------
extern "C" void kernel_launch(void* const* d_in, const int* in_sizes, int n_in,
                              void* d_out, int out_size)
{
    const float* x       = (const float*)d_in[0];
    const int*   eidx    = (const int*)d_in[1];
    const float* w1      = (const float*)d_in[2];
    const float* b1      = (const float*)d_in[3];
    const float* w2      = (const float*)d_in[4];
    const float* b2      = (const float*)d_in[5];
    const float* w3      = (const float*)d_in[6];
    const float* b3      = (const float*)d_in[7];
    const float* parsing = (const float*)d_in[8];
    const float* l0w     = (const float*)d_in[9];
    const float* l0b     = (const float*)d_in[10];
    const float* l1w     = (const float*)d_in[11];
    const float* l1b     = (const float*)d_in[12];
    const float* cw1     = (const float*)d_in[13];
    float* out = (float*)d_out;
    const int* erow = eidx;
    const int* ecol = eidx + N_EDGES;

    float *p_xt, *p_w1t, *p_w2t, *p_l0wt, *p_l1wt, *p_cw1t;
    float *p_h1, *p_h2, *p_glp, *p_Wcat, *p_bcat, *p_hA, *p_hB, *p_agg;
    int *p_cnt;
    cudaGetSymbolAddress((void**)&p_xt, g_xt);
    cudaGetSymbolAddress((void**)&p_w1t, g_w1t);
    cudaGetSymbolAddress((void**)&p_w2t, g_w2t);
    cudaGetSymbolAddress((void**)&p_l0wt, g_l0wt);
    cudaGetSymbolAddress((void**)&p_l1wt, g_l1wt);
    cudaGetSymbolAddress((void**)&p_cw1t, g_cw1t);
    cudaGetSymbolAddress((void**)&p_h1, g_h1);
    cudaGetSymbolAddress((void**)&p_h2, g_h2);
    cudaGetSymbolAddress((void**)&p_glp, g_glp);
    cudaGetSymbolAddress((void**)&p_Wcat, g_Wcat);
    cudaGetSymbolAddress((void**)&p_bcat, g_bcat);
    cudaGetSymbolAddress((void**)&p_hA, g_hA);
    cudaGetSymbolAddress((void**)&p_hB, g_hB);
    cudaGetSymbolAddress((void**)&p_agg, g_agg);
    cudaGetSymbolAddress((void**)&p_cnt, g_cnt);

    const int gmx = (N_NODES + 127) / 128;  // 391

    // tf32 pre-rounding of all MMA operand tensors
    rt_kernel<<<(N_NODES * IN_DIM + 255) / 256, 256>>>(x, p_xt, N_NODES * IN_DIM);
    rt_kernel<<<(IN_DIM * 512 + 255) / 256, 256>>>(w1, p_w1t, IN_DIM * 512);
    rt_kernel<<<(512 * OUT_DIM + 255) / 256, 256>>>(w2, p_w2t, 512 * OUT_DIM);
    rt_kernel<<<(IN_DIM * H_DIM + 255) / 256, 256>>>(l0w, p_l0wt, IN_DIM * H_DIM);
    rt_kernel<<<(H_DIM * OUT_DIM + 255) / 256, 256>>>(l1w, p_l1wt, H_DIM * OUT_DIM);
    rt_kernel<<<(2 * H_DIM * H_DIM + 255) / 256, 256>>>(cw1, p_cw1t, 2 * H_DIM * H_DIM);

    p_kernel<<<4, 1024>>>(parsing);
    wcat_kernel<<<17, 256>>>(w3, b3);

    // MLP: x -> h1 -> h2 -> [logits | lp]
    gemm_tc<<<dim3(gmx, 8), 256>>>(p_xt, p_w1t, b1, p_h1, N_NODES, 512, IN_DIM, 1.f, 0.f, 1, 1);
    gemm_tc<<<dim3(gmx, 1), 256>>>(p_h1, p_w2t, b2, p_h2, N_NODES, OUT_DIM, H1_DIM, 1.f, 0.f, 1, 1);
    gemm_tc<<<dim3(gmx, 2), 256>>>(p_h2, p_Wcat, p_bcat, p_glp, N_NODES, 128, OUT_DIM, 1.f, 0.f, 0, 0);
    // x0 = relu(x @ lin0 + b)
    gemm_tc<<<dim3(gmx, 2), 256>>>(p_xt, p_l0wt, l0b, p_hA, N_NODES, H_DIM, IN_DIM, 1.f, 0.f, 1, 1);

    // edge weights + stats
    ew_kernel<<<EW_BLOCKS, 256>>>(erow, ecol);
    stats_kernel<<<1, 1024>>>();

    // CSR build
    cudaMemsetAsync(p_cnt, 0, N_NODES * sizeof(int));
    count_kernel<<<(N_EDGES + 255) / 256, 256>>>(ecol);
    scan_kernel<<<1, 1024>>>();
    scatter_kernel<<<(N_EDGES + 255) / 256, 256>>>(erow, ecol);
    deg_kernel<<<(N_NODES + 7) / 8, 256>>>();
    normw_kernel<<<(N_NODES + 7) / 8, 256>>>();

    // layer 0
    spmm_kernel<<<(N_NODES + 7) / 8, 256>>>(p_hA, p_agg);
    gemm_tc<<<dim3(gmx, 2), 256>>>(p_agg, p_cw1t, nullptr, p_hB,
                                   N_NODES, H_DIM, H_DIM, BETA0, 1.f - BETA0, 1, 1);
    // layer 1
    spmm_kernel<<<(N_NODES + 7) / 8, 256>>>(p_hB, p_agg);
    gemm_tc<<<dim3(gmx, 2), 256>>>(p_agg, p_cw1t + H_DIM * H_DIM, nullptr, p_hA,
                                   N_NODES, H_DIM, H_DIM, BETA1, 1.f - BETA1, 1, 1);
    // output
    gemm_tc<<<dim3(gmx, 1), 256>>>(p_hA, p_l1wt, l1b, out, N_NODES, OUT_DIM, H_DIM, 1.f, 0.f, 0, 0);
}

// round 6
// speedup vs baseline: 1.2408x; 1.1062x over previous
#include <cuda_runtime.h>
#include <math.h>
#include <stdint.h>

// Problem constants (fixed by the reference)
#define N_NODES 50000
#define N_EDGES 800000
#define IN_DIM  128
#define H_DIM   128
#define OUT_DIM 64
#define H1_DIM  512
#define EW_BLOCKS ((N_EDGES * 16 + 255) / 256)   // 50000
#define SCAN_NB ((N_NODES + 511) / 512)          // 98

// alpha = 0.0 in reference -> x0/conv_w2 terms vanish.
#define BETA0 0.6931471805599453f   /* ln(2)   */
#define BETA1 0.4054651081081644f   /* ln(1.5) */

// ---------------- device scratch (static globals; no cudaMalloc allowed) ----
__device__ float  g_xt[N_NODES * IN_DIM];     // tf32-rounded x
__device__ float  g_w1t[IN_DIM * 512];
__device__ float  g_w2t[512 * OUT_DIM];
__device__ float  g_l0wt[IN_DIM * H_DIM];
__device__ float  g_l1wt[H_DIM * OUT_DIM];
__device__ float  g_cw1t[2 * H_DIM * H_DIM];
__device__ float  g_h1[N_NODES * H1_DIM];
__device__ float  g_h2[N_NODES * OUT_DIM];
__device__ float  g_glp[N_NODES * 128];   // [logits | lp] per row
__device__ float  g_P[OUT_DIM * OUT_DIM];
__device__ float  g_Wcat[OUT_DIM * 128];  // [w3 | w3@P], tf32-rounded
__device__ float  g_bcat[128];            // [b3 | b3@P]
__device__ float  g_hA[N_NODES * H_DIM];
__device__ float  g_hB[N_NODES * H_DIM];
__device__ float  g_agg[N_NODES * H_DIM];
__device__ float  g_ewraw[N_EDGES];
__device__ float  g_ewp[N_EDGES];
__device__ float  g_normw[N_EDGES];
__device__ int    g_esrc[N_EDGES];
__device__ int    g_cnt[N_NODES];
__device__ int    g_cursor[N_NODES];
__device__ int    g_rowptr[N_NODES + 1];
__device__ int    g_bsum[SCAN_NB + 1];
__device__ double g_psum[EW_BLOCKS];
__device__ double g_psum2[EW_BLOCKS];
__device__ float  g_stats[2];
__device__ float  g_dinv[N_NODES];

// ---------------- tf32 helpers ----------------------------------------------
__device__ __forceinline__ uint32_t f2tf32(float f)
{
    uint32_t o;
    asm("cvt.rna.tf32.f32 %0, %1;" : "=r"(o) : "f"(f));
    return o;
}
__device__ __forceinline__ float tf32r(float f) { return __uint_as_float(f2tf32(f)); }

__device__ __forceinline__ void mma_tf32(float d[4], const uint32_t a[4], const uint32_t b[2])
{
    asm volatile(
        "mma.sync.aligned.m16n8k8.row.col.f32.tf32.tf32.f32 "
        "{%0,%1,%2,%3}, {%4,%5,%6,%7}, {%8,%9}, {%0,%1,%2,%3};"
        : "+f"(d[0]), "+f"(d[1]), "+f"(d[2]), "+f"(d[3])
        : "r"(a[0]), "r"(a[1]), "r"(a[2]), "r"(a[3]), "r"(b[0]), "r"(b[1]));
}

__device__ __forceinline__ void cpa16(uint32_t dst, const float* src, uint32_t sz)
{
    asm volatile("cp.async.cg.shared.global [%0], [%1], 16, %2;"
                 :: "r"(dst), "l"(src), "r"(sz));
}
__device__ __forceinline__ void cpa_commit() { asm volatile("cp.async.commit_group;"); }
__device__ __forceinline__ void cpa_wait1()  { asm volatile("cp.async.wait_group 1;"); }

// ---------------- tf32 tensor-core GEMM (cp.async 3-stage) ------------------
// C = relu?( alpha*(A@B) + bias + addA*A ) [+ tf32 rounding of output]
// A, B must already be tf32-rounded fp32.
// TNQ=1: BN=64,  warp tile 32x32, 3 CTAs/SM.
// TNQ=2: BN=128, warp tile 32x64, 2 CTAs/SM (dynamic smem 56.8KB).
// smem: A [m][k] stride 20, B [k][n] stride BN+8 (conflict-free frag loads).

#define SKA 20
#define A_WORDS (128 * SKA)   // 2560

template<int TNQ>
__global__ __launch_bounds__(256, 4 - TNQ)
void gemm_tc(const float* __restrict__ A, const float* __restrict__ B,
             const float* __restrict__ bias, float* __restrict__ C,
             int M, int N, int K, float alpha, float addA, int do_relu, int round_out)
{
    constexpr int BN  = 64 * TNQ;
    constexpr int SKB = BN + 8;
    constexpr int B_WORDS = 16 * SKB;
    extern __shared__ float smem[];
    float* As = smem;
    float* Bs = smem + 3 * A_WORDS;

    const int tid  = threadIdx.x;
    const int lane = tid & 31;
    const int wid  = tid >> 5;
    const int wm   = wid & 3;
    const int wn   = wid >> 2;
    const int gid  = lane >> 2;
    const int tig  = lane & 3;
    const int m0   = blockIdx.x * 128;
    const int n0   = blockIdx.y * BN;

    // staging roles
    const int am     = tid >> 1;            // A row 0..127
    const int akq    = (tid & 1) * 2;       // chunks akq, akq+1
    const uint32_t asz = ((m0 + am) < M) ? 16u : 0u;
    const float* Apt = A + (size_t)(m0 + am) * K + akq * 4;
    const int bk     = tid >> 4;            // B k-row 0..15
    const int bnq    = (tid & 15) * 4 * TNQ;
    const float* Bpt = B + (size_t)bk * N + n0 + bnq;

    uint32_t as_base = (uint32_t)__cvta_generic_to_shared(As);
    uint32_t bs_base = (uint32_t)__cvta_generic_to_shared(Bs);
    const uint32_t adst0 = as_base + (am * SKA + akq * 4) * 4;
    const uint32_t bdst0 = bs_base + (bk * SKB + bnq) * 4;

    float d[2][4 * TNQ][4];
#pragma unroll
    for (int f = 0; f < 2; f++)
#pragma unroll
        for (int g = 0; g < 4 * TNQ; g++)
#pragma unroll
            for (int i = 0; i < 4; i++) d[f][g][i] = 0.f;

    const int ntiles = K >> 4;

    // prefetch tiles 0 and 1
#pragma unroll
    for (int t = 0; t < 2; t++) {
        const uint32_t ad = adst0 + t * (A_WORDS * 4);
        const uint32_t bd = bdst0 + t * (B_WORDS * 4);
        cpa16(ad, Apt + t * 16, asz);
        cpa16(ad + 16, Apt + t * 16 + 4, asz);
#pragma unroll
        for (int q = 0; q < TNQ; q++)
            cpa16(bd + q * 16, Bpt + (size_t)t * 16 * N + q * 4, 16);
        cpa_commit();
    }
    cpa_wait1();
    __syncthreads();

    for (int t = 0; t < ntiles; t++) {
        // issue tile t+2 into slot (t+2)%3
        const int tp = t + 2;
        if (tp < ntiles) {
            const int sl = tp - (tp / 3) * 3;
            const uint32_t ad = adst0 + sl * (A_WORDS * 4);
            const uint32_t bd = bdst0 + sl * (B_WORDS * 4);
            cpa16(ad, Apt + tp * 16, asz);
            cpa16(ad + 16, Apt + tp * 16 + 4, asz);
#pragma unroll
            for (int q = 0; q < TNQ; q++)
                cpa16(bd + q * 16, Bpt + (size_t)tp * 16 * N + q * 4, 16);
        }
        cpa_commit();

        // compute tile t from slot t%3
        const int s = t - (t / 3) * 3;
        const float* Ab = As + s * A_WORDS;
        const float* Bb = Bs + s * B_WORDS;
#pragma unroll
        for (int ks = 0; ks < 16; ks += 8) {
            uint32_t af[2][4];
#pragma unroll
            for (int f = 0; f < 2; f++) {
                const int rb = wm * 32 + f * 16 + gid;
                af[f][0] = __float_as_uint(Ab[rb * SKA + ks + tig]);
                af[f][1] = __float_as_uint(Ab[(rb + 8) * SKA + ks + tig]);
                af[f][2] = __float_as_uint(Ab[rb * SKA + ks + tig + 4]);
                af[f][3] = __float_as_uint(Ab[(rb + 8) * SKA + ks + tig + 4]);
            }
            uint32_t bf[4 * TNQ][2];
#pragma unroll
            for (int g = 0; g < 4 * TNQ; g++) {
                const int nb = wn * 32 * TNQ + g * 8 + gid;
                bf[g][0] = __float_as_uint(Bb[(ks + tig) * SKB + nb]);
                bf[g][1] = __float_as_uint(Bb[(ks + tig + 4) * SKB + nb]);
            }
#pragma unroll
            for (int f = 0; f < 2; f++)
#pragma unroll
                for (int g = 0; g < 4 * TNQ; g++)
                    mma_tf32(d[f][g], af[f], bf[g]);
        }
        cpa_wait1();
        __syncthreads();
    }

    // epilogue
#pragma unroll
    for (int f = 0; f < 2; f++) {
        const int r0 = m0 + wm * 32 + f * 16 + gid;
#pragma unroll
        for (int g = 0; g < 4 * TNQ; g++) {
            const int cc = n0 + wn * 32 * TNQ + g * 8 + 2 * tig;
#pragma unroll
            for (int h = 0; h < 2; h++) {
                const int gm = r0 + h * 8;
                if (gm >= M) continue;
                float v0 = alpha * d[f][g][2 * h + 0];
                float v1 = alpha * d[f][g][2 * h + 1];
                if (bias) {
                    float2 bb = *(const float2*)&bias[cc];
                    v0 += bb.x; v1 += bb.y;
                }
                if (addA != 0.f) {  // residual path: N == K
                    float2 r = *(const float2*)&A[(size_t)gm * K + cc];
                    v0 += addA * r.x; v1 += addA * r.y;
                }
                if (do_relu) { v0 = fmaxf(v0, 0.f); v1 = fmaxf(v1, 0.f); }
                if (round_out) { v0 = tf32r(v0); v1 = tf32r(v1); }
                *(float2*)&C[(size_t)gm * N + cc] = make_float2(v0, v1);
            }
        }
    }
}

// ---------------- fused tf32 rounding of all operand tensors ----------------
#define RT_N0 (N_NODES * IN_DIM)                 // x      6,400,000
#define RT_N1 (RT_N0 + IN_DIM * 512)             // w1
#define RT_N2 (RT_N1 + 512 * OUT_DIM)            // w2
#define RT_N3 (RT_N2 + IN_DIM * H_DIM)           // l0w
#define RT_N4 (RT_N3 + H_DIM * OUT_DIM)          // l1w
#define RT_N5 (RT_N4 + 2 * H_DIM * H_DIM)        // cw1
__global__ void rtall_kernel(const float* __restrict__ x, const float* __restrict__ w1,
                             const float* __restrict__ w2, const float* __restrict__ l0w,
                             const float* __restrict__ l1w, const float* __restrict__ cw1)
{
    int i = blockIdx.x * 256 + threadIdx.x;
    if (i < RT_N0)      g_xt[i] = tf32r(x[i]);
    else if (i < RT_N1) g_w1t[i - RT_N0] = tf32r(w1[i - RT_N0]);
    else if (i < RT_N2) g_w2t[i - RT_N1] = tf32r(w2[i - RT_N1]);
    else if (i < RT_N3) g_l0wt[i - RT_N2] = tf32r(l0w[i - RT_N2]);
    else if (i < RT_N4) g_l1wt[i - RT_N3] = tf32r(l1w[i - RT_N3]);
    else if (i < RT_N5) g_cw1t[i - RT_N4] = tf32r(cw1[i - RT_N4]);
}

// ---------------- P = relu(SCALE * parsing[0]) ----------------
__global__ void p_kernel(const float* __restrict__ parsing)
{
    int i = blockIdx.x * blockDim.x + threadIdx.x;
    if (i < OUT_DIM * OUT_DIM) g_P[i] = fmaxf(2.0f * parsing[i], 0.0f);
}

// ---------------- Wcat = [w3 | w3@P], bcat = [b3 | b3@P] (tf32-rounded W) ---
__global__ void wcat_kernel(const float* __restrict__ w3, const float* __restrict__ b3)
{
    int idx = blockIdx.x * 256 + threadIdx.x;
    if (idx < 64 * 64) {
        int k = idx >> 6, j = idx & 63;
        g_Wcat[k * 128 + j] = tf32r(w3[k * 64 + j]);
        float s = 0.f;
        for (int i = 0; i < 64; i++) s += w3[k * 64 + i] * g_P[i * 64 + j];
        g_Wcat[k * 128 + 64 + j] = tf32r(s);
    } else if (idx < 64 * 64 + 64) {
        int j = idx - 64 * 64;
        g_bcat[j] = b3[j];
        float s = 0.f;
        for (int i = 0; i < 64; i++) s += b3[i] * g_P[i * 64 + j];
        g_bcat[64 + j] = s;
    }
}

// -------- edge weights + in-degree count (fused): ew, partial stats, cnt ----
__global__ void ew_kernel(const int* __restrict__ erow, const int* __restrict__ ecol)
{
    int t = blockIdx.x * 256 + threadIdx.x;
    int e = t >> 4;
    int l = t & 15;
    float v = 0.f;
    int c = -1;
    if (e < N_EDGES) {
        int r = erow[e];
        c = ecol[e];
        float4 a = *(const float4*)(g_glp + (size_t)r * 128 + l * 4);
        float4 b = *(const float4*)(g_glp + (size_t)c * 128 + 64 + l * 4);
        v = a.x * b.x + a.y * b.y + a.z * b.z + a.w * b.w;
    }
#pragma unroll
    for (int off = 8; off > 0; off >>= 1)
        v += __shfl_xor_sync(0xffffffffu, v, off);
    if (l == 0 && e < N_EDGES) {
        g_ewraw[e] = v;
        atomicAdd(&g_cnt[c], 1);
    }

    double s  = (l == 0 && e < N_EDGES) ? (double)v : 0.0;
    double s2 = (l == 0 && e < N_EDGES) ? (double)v * (double)v : 0.0;
    __shared__ double sh1[256];
    __shared__ double sh2[256];
    sh1[threadIdx.x] = s; sh2[threadIdx.x] = s2;
    __syncthreads();
    for (int off = 128; off > 0; off >>= 1) {
        if (threadIdx.x < off) {
            sh1[threadIdx.x] += sh1[threadIdx.x + off];
            sh2[threadIdx.x] += sh2[threadIdx.x + off];
        }
        __syncthreads();
    }
    if (threadIdx.x == 0) { g_psum[blockIdx.x] = sh1[0]; g_psum2[blockIdx.x] = sh2[0]; }
}

__global__ void stats_kernel()
{
    int t = threadIdx.x;
    double s = 0.0, s2 = 0.0;
    for (int i = t; i < EW_BLOCKS; i += 1024) { s += g_psum[i]; s2 += g_psum2[i]; }
    __shared__ double sh1[1024];
    __shared__ double sh2[1024];
    sh1[t] = s; sh2[t] = s2;
    __syncthreads();
    for (int off = 512; off > 0; off >>= 1) {
        if (t < off) { sh1[t] += sh1[t + off]; sh2[t] += sh2[t + off]; }
        __syncthreads();
    }
    if (t == 0) {
        double sum = sh1[0], sumsq = sh2[0];
        double mean = sum / (double)N_EDGES;
        double var = (sumsq - sum * sum / (double)N_EDGES) / (double)(N_EDGES - 1);
        g_stats[0] = (float)mean;
        g_stats[1] = (float)sqrt(1e-4 / var);
    }
}

// ---------------- parallel 3-phase scan of g_cnt -> g_rowptr, g_cursor ------
__global__ void scanA_kernel()
{
    __shared__ int sh[512];
    int b = blockIdx.x, t = threadIdx.x;
    int i = b * 512 + t;
    int v = (i < N_NODES) ? g_cnt[i] : 0;
    sh[t] = v;
    __syncthreads();
    for (int off = 1; off < 512; off <<= 1) {
        int add = (t >= off) ? sh[t - off] : 0;
        __syncthreads();
        sh[t] += add;
        __syncthreads();
    }
    if (i < N_NODES) g_rowptr[i + 1] = sh[t];   // block-local inclusive
    if (t == 511) g_bsum[b] = sh[511];
}

__global__ void scanB_kernel()
{
    __shared__ int sh[SCAN_NB];
    int t = threadIdx.x;
    if (t < SCAN_NB) sh[t] = g_bsum[t];
    __syncthreads();
    if (t == 0) {
        int run = 0;
        for (int b = 0; b < SCAN_NB; b++) { int x = sh[b]; sh[b] = run; run += x; }
    }
    __syncthreads();
    if (t < SCAN_NB) g_bsum[t] = sh[t];         // exclusive block offsets
}

__global__ void scanC_kernel()
{
    int b = blockIdx.x, t = threadIdx.x;
    int i = b * 512 + t;
    if (i < N_NODES) {
        int incl = g_rowptr[i + 1] + g_bsum[b];
        g_rowptr[i + 1] = incl;
        g_cursor[i] = incl - g_cnt[i];
        if (i == 0) g_rowptr[0] = 0;
    }
}

__global__ void scatter_kernel(const int* __restrict__ erow, const int* __restrict__ ecol)
{
    int e = blockIdx.x * blockDim.x + threadIdx.x;
    if (e < N_EDGES) {
        int p = atomicAdd(&g_cursor[ecol[e]], 1);
        g_esrc[p] = erow[e];
        g_ewp[p] = g_ewraw[e];
    }
}

__global__ void deg_kernel()
{
    int warp = (blockIdx.x * blockDim.x + threadIdx.x) >> 5;
    int lane = threadIdx.x & 31;
    if (warp >= N_NODES) return;
    float mean = g_stats[0], scale = g_stats[1];
    int s0 = g_rowptr[warp], s1 = g_rowptr[warp + 1];
    float s = 0.f;
    for (int p = s0 + lane; p < s1; p += 32) {
        float w = (g_ewp[p] - mean) * scale + 1.0f;
        g_ewp[p] = w;
        s += w;
    }
#pragma unroll
    for (int off = 16; off > 0; off >>= 1)
        s += __shfl_xor_sync(0xffffffffu, s, off);
    if (lane == 0) {
        float deg = s + 1.0f;
        g_dinv[warp] = (deg > 0.f) ? rsqrtf(deg) : 0.f;
    }
}

__global__ void normw_kernel()
{
    int warp = (blockIdx.x * blockDim.x + threadIdx.x) >> 5;
    int lane = threadIdx.x & 31;
    if (warp >= N_NODES) return;
    float di = g_dinv[warp];
    int s0 = g_rowptr[warp], s1 = g_rowptr[warp + 1];
    for (int p = s0 + lane; p < s1; p += 32)
        g_normw[p] = g_dinv[g_esrc[p]] * g_ewp[p] * di;
}

// ---- SpMM: agg[n] = tf32round( sum_in normw*h[src] + dinv[n]^2 * h[n] ) ----
__global__ void spmm_kernel(const float* __restrict__ hin, float* __restrict__ agg)
{
    int warp = (blockIdx.x * blockDim.x + threadIdx.x) >> 5;
    int lane = threadIdx.x & 31;
    if (warp >= N_NODES) return;
    const float4* h4 = (const float4*)hin;
    float di = g_dinv[warp];
    float selfw = di * di;
    float4 hv = h4[(size_t)warp * 32 + lane];
    float4 acc;
    acc.x = selfw * hv.x; acc.y = selfw * hv.y; acc.z = selfw * hv.z; acc.w = selfw * hv.w;
    int s0 = g_rowptr[warp], s1 = g_rowptr[warp + 1];
    for (int p = s0; p < s1; p++) {
        float w = g_normw[p];
        int src = g_esrc[p];
        float4 v = h4[(size_t)src * 32 + lane];
        acc.x += w * v.x; acc.y += w * v.y; acc.z += w * v.z; acc.w += w * v.w;
    }
    acc.x = tf32r(acc.x); acc.y = tf32r(acc.y);
    acc.z = tf32r(acc.z); acc.w = tf32r(acc.w);
    ((float4*)agg)[(size_t)warp * 32 + lane] = acc;
}

// ---------------- launch ----------------------------------------------------
extern "C" void kernel_launch(void* const* d_in, const int* in_sizes, int n_in,
                              void* d_out, int out_size)
{
    const float* x       = (const float*)d_in[0];
    const int*   eidx    = (const int*)d_in[1];
    const float* w1      = (const float*)d_in[2];
    const float* b1      = (const float*)d_in[3];
    const float* w2      = (const float*)d_in[4];
    const float* b2      = (const float*)d_in[5];
    const float* w3      = (const float*)d_in[6];
    const float* b3      = (const float*)d_in[7];
    const float* parsing = (const float*)d_in[8];
    const float* l0w     = (const float*)d_in[9];
    const float* l0b     = (const float*)d_in[10];
    const float* l1w     = (const float*)d_in[11];
    const float* l1b     = (const float*)d_in[12];
    const float* cw1     = (const float*)d_in[13];
    float* out = (float*)d_out;
    const int* erow = eidx;
    const int* ecol = eidx + N_EDGES;

    float *p_xt, *p_w1t, *p_w2t, *p_l0wt, *p_l1wt, *p_cw1t;
    float *p_h1, *p_h2, *p_glp, *p_Wcat, *p_bcat, *p_hA, *p_hB, *p_agg;
    int *p_cnt;
    cudaGetSymbolAddress((void**)&p_xt, g_xt);
    cudaGetSymbolAddress((void**)&p_w1t, g_w1t);
    cudaGetSymbolAddress((void**)&p_w2t, g_w2t);
    cudaGetSymbolAddress((void**)&p_l0wt, g_l0wt);
    cudaGetSymbolAddress((void**)&p_l1wt, g_l1wt);
    cudaGetSymbolAddress((void**)&p_cw1t, g_cw1t);
    cudaGetSymbolAddress((void**)&p_h1, g_h1);
    cudaGetSymbolAddress((void**)&p_h2, g_h2);
    cudaGetSymbolAddress((void**)&p_glp, g_glp);
    cudaGetSymbolAddress((void**)&p_Wcat, g_Wcat);
    cudaGetSymbolAddress((void**)&p_bcat, g_bcat);
    cudaGetSymbolAddress((void**)&p_hA, g_hA);
    cudaGetSymbolAddress((void**)&p_hB, g_hB);
    cudaGetSymbolAddress((void**)&p_agg, g_agg);
    cudaGetSymbolAddress((void**)&p_cnt, g_cnt);

    const int gmx = (N_NODES + 127) / 128;  // 391
    const int SM1 = 3 * (A_WORDS + 16 * 72)  * 4;   // 44544 B, TNQ=1
    const int SM2 = 3 * (A_WORDS + 16 * 136) * 4;   // 56832 B, TNQ=2
    cudaFuncSetAttribute(gemm_tc<2>, cudaFuncAttributeMaxDynamicSharedMemorySize, SM2);

    // setup: tf32 rounding, P, Wcat, zero counters
    rtall_kernel<<<(RT_N5 + 255) / 256, 256>>>(x, w1, w2, l0w, l1w, cw1);
    p_kernel<<<4, 1024>>>(parsing);
    wcat_kernel<<<17, 256>>>(w3, b3);
    cudaMemsetAsync(p_cnt, 0, N_NODES * sizeof(int));

    // MLP: x -> h1 -> h2 -> [logits | lp]
    gemm_tc<2><<<dim3(gmx, 4), 256, SM2>>>(p_xt, p_w1t, b1, p_h1, N_NODES, 512, IN_DIM, 1.f, 0.f, 1, 1);
    gemm_tc<1><<<dim3(gmx, 1), 256, SM1>>>(p_h1, p_w2t, b2, p_h2, N_NODES, OUT_DIM, H1_DIM, 1.f, 0.f, 1, 1);
    gemm_tc<2><<<dim3(gmx, 1), 256, SM2>>>(p_h2, p_Wcat, p_bcat, p_glp, N_NODES, 128, OUT_DIM, 1.f, 0.f, 0, 0);
    // x0 = relu(x @ lin0 + b)
    gemm_tc<2><<<dim3(gmx, 1), 256, SM2>>>(p_xt, p_l0wt, l0b, p_hA, N_NODES, H_DIM, IN_DIM, 1.f, 0.f, 1, 1);

    // edge weights + per-node counts + stats
    ew_kernel<<<EW_BLOCKS, 256>>>(erow, ecol);
    stats_kernel<<<1, 1024>>>();

    // CSR build (parallel scan)
    scanA_kernel<<<SCAN_NB, 512>>>();
    scanB_kernel<<<1, 128>>>();
    scanC_kernel<<<SCAN_NB, 512>>>();
    scatter_kernel<<<(N_EDGES + 255) / 256, 256>>>(erow, ecol);
    deg_kernel<<<(N_NODES + 7) / 8, 256>>>();
    normw_kernel<<<(N_NODES + 7) / 8, 256>>>();

    // layer 0
    spmm_kernel<<<(N_NODES + 7) / 8, 256>>>(p_hA, p_agg);
    gemm_tc<2><<<dim3(gmx, 1), 256, SM2>>>(p_agg, p_cw1t, nullptr, p_hB,
                                           N_NODES, H_DIM, H_DIM, BETA0, 1.f - BETA0, 1, 1);
    // layer 1
    spmm_kernel<<<(N_NODES + 7) / 8, 256>>>(p_hB, p_agg);
    gemm_tc<2><<<dim3(gmx, 1), 256, SM2>>>(p_agg, p_cw1t + H_DIM * H_DIM, nullptr, p_hA,
                                           N_NODES, H_DIM, H_DIM, BETA1, 1.f - BETA1, 1, 1);
    // output
    gemm_tc<1><<<dim3(gmx, 1), 256, SM1>>>(p_hA, p_l1wt, l1b, out, N_NODES, OUT_DIM, H_DIM, 1.f, 0.f, 0, 0);
}